// round 13
// baseline (speedup 1.0000x reference)
#include <cuda_runtime.h>
#include <cuda_bf16.h>
#include <math.h>
#include <stdint.h>

// SofaNetEllipse R12: HMMA 3-term bf16 hi/lo, two independent N-half pipelines
// synchronized by named barriers (overlap: one half's epilogue vs other half's
// GEMM). W1/W2 fragments loaded straight from pre-split global bf16 (no A smem,
// no cp.async stages). __sincosf for the trig tail.

typedef unsigned long long ull;

namespace {
constexpr int HD = 128, NCUR = 128, LFULL = 4097, BHALF = 2049, BT = 128;
constexpr int NTILES   = 17;
constexpr int NTHREADS = 512;
constexpr int BKB = 528;                 // B k-row stride, bytes (256 c-cols * 2B + 16 pad)
constexpr int OFF_BHI = 0;
constexpr int OFF_BLO = OFF_BHI + HD * BKB;   // 67584
constexpr int OFF_SCR = 0;               // layer-3 scratch float2[s][i], aliases all of B
constexpr int SCRS = 129;                // scratch row stride (float2 units) -> 132096 B
constexpr int OFF_RED = 135168;          // reduction arrays (past B end)
constexpr int SMEM_BYTES = OFF_RED + 4096;    // 139264
}

// pre-split bf16 weights (written by prologue kernel each launch)
__device__ __nv_bfloat16 g_w1hi[NCUR * HD * HD];
__device__ __nv_bfloat16 g_w1lo[NCUR * HD * HD];
__device__ __nv_bfloat16 g_w2hi[NCUR * HD * HD];
__device__ __nv_bfloat16 g_w2lo[NCUR * HD * HD];

__device__ __forceinline__ uint32_t smem_u32(const void* p) {
    uint32_t a;
    asm("{ .reg .u64 t; cvta.to.shared.u64 t, %1; cvt.u32.u64 %0, t; }" : "=r"(a) : "l"(p));
    return a;
}
__device__ __forceinline__ void ldsm4t(uint32_t (&r)[4], uint32_t addr) {
    asm volatile("ldmatrix.sync.aligned.m8n8.x4.trans.shared.b16 {%0,%1,%2,%3}, [%4];"
                 : "=r"(r[0]), "=r"(r[1]), "=r"(r[2]), "=r"(r[3]) : "r"(addr));
}
__device__ __forceinline__ void stsm4(uint32_t addr, uint32_t r0, uint32_t r1,
                                      uint32_t r2, uint32_t r3) {
    asm volatile("stmatrix.sync.aligned.m8n8.x4.shared.b16 [%0], {%1,%2,%3,%4};"
                 :: "r"(addr), "r"(r0), "r"(r1), "r"(r2), "r"(r3) : "memory");
}
__device__ __forceinline__ void mma_bf16(float (&d)[4], const uint32_t (&a)[4],
                                         uint32_t b0, uint32_t b1) {
    asm volatile(
        "mma.sync.aligned.m16n8k16.row.col.f32.bf16.bf16.f32 "
        "{%0,%1,%2,%3}, {%4,%5,%6,%7}, {%8,%9}, {%0,%1,%2,%3};"
        : "+f"(d[0]), "+f"(d[1]), "+f"(d[2]), "+f"(d[3])
        : "r"(a[0]), "r"(a[1]), "r"(a[2]), "r"(a[3]), "r"(b0), "r"(b1));
}
__device__ __forceinline__ void half_bar(int half) {
    asm volatile("bar.sync %0, 256;" :: "r"(1 + half) : "memory");
}
__device__ __forceinline__ uint32_t packh(__nv_bfloat16 a, __nv_bfloat16 b) {
    uint16_t ua = *(uint16_t*)&a, ub = *(uint16_t*)&b;
    return (uint32_t)ua | ((uint32_t)ub << 16);
}
__device__ __forceinline__ void split2(float x, float y, uint32_t& hi, uint32_t& lo) {
    const __nv_bfloat16 hx = __float2bfloat16(x), hy = __float2bfloat16(y);
    const __nv_bfloat16 lx = __float2bfloat16(x - __bfloat162float(hx));
    const __nv_bfloat16 ly = __float2bfloat16(y - __bfloat162float(hy));
    hi = packh(hx, hy);
    lo = packh(lx, ly);
}

// ---- prologue: split fp32 W1/W2 into bf16 hi/lo global buffers
__global__ void split_w_kernel(const float* __restrict__ w1, const float* __restrict__ w2) {
    const int idx = blockIdx.x * blockDim.x + threadIdx.x;
    if (idx < NCUR * HD * HD) {
        float v = w1[idx];
        __nv_bfloat16 h = __float2bfloat16(v);
        g_w1hi[idx] = h;
        g_w1lo[idx] = __float2bfloat16(v - __bfloat162float(h));
        v = w2[idx];
        h = __float2bfloat16(v);
        g_w2hi[idx] = h;
        g_w2lo[idx] = __float2bfloat16(v - __bfloat162float(h));
    }
}

// One layer GEMM, W fragments via LDG from pre-split global (L2/L1 resident),
// double-buffered one k-step ahead. B from smem [k][c] via ldmatrix.trans.
// Fragment mapping identical to the verified ldsm4-from-[i][k] layout:
//  a0=(g8, 2t4), a1=(g8+8, 2t4), a2=(g8, 2t4+8), a3=(g8+8, 2t4+8), k-tile +16/kk.
__device__ __forceinline__ void gemm_layer_ldg(float (&acc)[16][4], uint32_t sb,
                                               const __nv_bfloat16* __restrict__ ghi,
                                               const __nv_bfloat16* __restrict__ glo,
                                               int mt, int nq, int lane) {
    const int row = 16 * mt + (lane >> 2);
    const int kc  = 2 * (lane & 3);
    const __nv_bfloat16* ph = ghi + row * HD + kc;
    const __nv_bfloat16* pl = glo + row * HD + kc;

    const int krow = (lane & 7) + (lane & 8);
    const int colb = 128 * nq + ((lane & 16) >> 1);
    const uint32_t b_off = (uint32_t)(krow * BKB) + (uint32_t)(colb * 2);
    const uint32_t b_hi = sb + OFF_BHI + b_off;
    const uint32_t b_lo = sb + OFF_BLO + b_off;

    uint32_t cah[4], cal[4];
#pragma unroll
    for (int q = 0; q < 4; q++) {
        const int o = ((q & 1) ? 8 * HD : 0) + ((q & 2) ? 8 : 0);
        cah[q] = __ldg((const uint32_t*)(ph + o));
        cal[q] = __ldg((const uint32_t*)(pl + o));
    }

#pragma unroll
    for (int kk = 0; kk < 8; kk++) {
        uint32_t nah[4], nal[4];
        if (kk < 7) {
            const int kb = 16 * (kk + 1);
#pragma unroll
            for (int q = 0; q < 4; q++) {
                const int o = kb + ((q & 1) ? 8 * HD : 0) + ((q & 2) ? 8 : 0);
                nah[q] = __ldg((const uint32_t*)(ph + o));
                nal[q] = __ldg((const uint32_t*)(pl + o));
            }
        }
        const uint32_t kb_s = (uint32_t)kk * (16u * BKB);
#pragma unroll
        for (int g = 0; g < 4; g++) {
            const uint32_t go = kb_s + (uint32_t)(64 * g);
            uint32_t bh0[4], bh1[4], bl0[4], bl1[4];
            ldsm4t(bh0, b_hi + go);
            ldsm4t(bh1, b_hi + go + 32u);
            ldsm4t(bl0, b_lo + go);
            ldsm4t(bl1, b_lo + go + 32u);
            mma_bf16(acc[4 * g + 0], cah, bh0[0], bh0[1]);
            mma_bf16(acc[4 * g + 1], cah, bh0[2], bh0[3]);
            mma_bf16(acc[4 * g + 2], cah, bh1[0], bh1[1]);
            mma_bf16(acc[4 * g + 3], cah, bh1[2], bh1[3]);
            mma_bf16(acc[4 * g + 0], cal, bh0[0], bh0[1]);
            mma_bf16(acc[4 * g + 1], cal, bh0[2], bh0[3]);
            mma_bf16(acc[4 * g + 2], cal, bh1[0], bh1[1]);
            mma_bf16(acc[4 * g + 3], cal, bh1[2], bh1[3]);
            mma_bf16(acc[4 * g + 0], cah, bl0[0], bl0[1]);
            mma_bf16(acc[4 * g + 1], cah, bl0[2], bl0[3]);
            mma_bf16(acc[4 * g + 2], cah, bl1[0], bl1[1]);
            mma_bf16(acc[4 * g + 3], cah, bl1[2], bl1[3]);
        }
        if (kk < 7) {
#pragma unroll
            for (int q = 0; q < 4; q++) { cah[q] = nah[q]; cal[q] = nal[q]; }
        }
    }
}

__global__ void __launch_bounds__(NTHREADS, 1)
sofa_kernel(const float* __restrict__ alpha,
            const float* __restrict__ w0g, const float* __restrict__ w3g,
            const float* __restrict__ b0g, const float* __restrict__ b1g,
            const float* __restrict__ b2g, const float* __restrict__ b3g,
            const float* __restrict__ sqrtag, float* __restrict__ out) {
    extern __shared__ char smem[];
    const uint32_t sb = smem_u32(smem);
    const int tid = threadIdx.x;
    const int wid = tid >> 5, lane = tid & 31;
    const int mt = wid & 7, nq = wid >> 3;          // warp = (M-tile, N-half)
    const int g8 = lane >> 2, t4 = lane & 3;        // D frag coords
    const int half = tid >> 8;                      // == nq for GEMM warps
    const int n = blockIdx.y, tile = blockIdx.x, base = tile * BT;
    const size_t woff = (size_t)n * HD * HD;

    // ---- layer 0: each half fills its own 128 c-cols of B (STS.128 pairs)
    {
        const int t256 = tid & 255;
        const float* w0n = w0g + n * HD;
        const float* b0n = b0g + n * HD;
#pragma unroll 1
        for (int it = 0; it < 4; it++) {
            const int task = t256 + 256 * it;       // 0..1023
            const int j = task >> 3, sgl = task & 7;
            const float w = w0n[j], bb = b0n[j];
            uint32_t hw[8], lw[8];
#pragma unroll
            for (int q = 0; q < 8; q++) {
                const float a = alpha[base + 64 * half + sgl * 8 + q];  // < 4097
                const float pre = fmaf(w, a, bb);
                const float h = pre > 0.f ? pre : 0.f;
                const float d = pre > 0.f ? w : 0.f;
                split2(h, d, hw[q], lw[q]);
            }
            const int rowb = j * BKB + half * 256 + sgl * 32;
            *(uint4*)(smem + OFF_BHI + rowb)      = make_uint4(hw[0], hw[1], hw[2], hw[3]);
            *(uint4*)(smem + OFF_BHI + rowb + 16) = make_uint4(hw[4], hw[5], hw[6], hw[7]);
            *(uint4*)(smem + OFF_BLO + rowb)      = make_uint4(lw[0], lw[1], lw[2], lw[3]);
            *(uint4*)(smem + OFF_BLO + rowb + 16) = make_uint4(lw[4], lw[5], lw[6], lw[7]);
        }
    }
    half_bar(half);

    // ---- layer 1 GEMM (W1 via LDG)
    float acc[16][4];
#pragma unroll
    for (int a_ = 0; a_ < 16; a_++)
#pragma unroll
        for (int b_ = 0; b_ < 4; b_++) acc[a_][b_] = 0.f;
    gemm_layer_ldg(acc, sb, g_w1hi + woff, g_w1lo + woff, mt, nq, lane);
    half_bar(half);   // own half's B reads done before overwrite

    // ---- layer-1 epilogue via stmatrix into own half's B columns
    {
        const int i0 = 16 * mt + g8;
        const float bias0 = b1g[n * HD + i0];
        const float bias1 = b1g[n * HD + i0 + 8];
        const int h8 = (lane >> 3) & 1, v8 = (lane >> 4) & 1, lr = lane & 7;
        const uint32_t st_hi = sb + OFF_BHI
            + (uint32_t)((16 * mt + 8 * h8 + lr) * BKB) + (uint32_t)((128 * nq + 8 * v8) * 2);
        const uint32_t st_lo = st_hi + (uint32_t)(OFF_BLO - OFF_BHI);
#pragma unroll
        for (int v = 0; v < 16; v += 2) {
            uint32_t h0, h1, h2, h3, l0, l1, l2, l3;
            {
                const float p = acc[v][0] + bias0;
                split2(p > 0.f ? p : 0.f, p > 0.f ? acc[v][1] : 0.f, h0, l0);
            }
            {
                const float p = acc[v][2] + bias1;
                split2(p > 0.f ? p : 0.f, p > 0.f ? acc[v][3] : 0.f, h1, l1);
            }
            {
                const float p = acc[v + 1][0] + bias0;
                split2(p > 0.f ? p : 0.f, p > 0.f ? acc[v + 1][1] : 0.f, h2, l2);
            }
            {
                const float p = acc[v + 1][2] + bias1;
                split2(p > 0.f ? p : 0.f, p > 0.f ? acc[v + 1][3] : 0.f, h3, l3);
            }
            stsm4(st_hi + (uint32_t)(v * 16), h0, h1, h2, h3);
            stsm4(st_lo + (uint32_t)(v * 16), l0, l1, l2, l3);
        }
    }
    half_bar(half);

    // ---- layer 2 GEMM (W2 via LDG)
#pragma unroll
    for (int a_ = 0; a_ < 16; a_++)
#pragma unroll
        for (int b_ = 0; b_ < 4; b_++) acc[a_][b_] = 0.f;
    gemm_layer_ldg(acc, sb, g_w2hi + woff, g_w2lo + woff, mt, nq, lane);
    __syncthreads();    // BOTH halves done reading B; scratch aliases B

    // ---- layer-2 epilogue: fp32 {h2, dh2} -> scratch [s][i]
    {
        float2* scr = (float2*)(smem + OFF_SCR);
        const int i0 = 16 * mt + g8, i1 = i0 + 8;
        const float bias0 = b2g[n * HD + i0];
        const float bias1 = b2g[n * HD + i1];
#pragma unroll
        for (int nt = 0; nt < 16; nt++) {
            const int s = 64 * nq + 4 * nt + t4;
            const float p0 = acc[nt][0] + bias0;
            const float h0 = p0 > 0.f ? p0 : 0.f;
            const float d0 = p0 > 0.f ? acc[nt][1] : 0.f;
            const float p1 = acc[nt][2] + bias1;
            const float h1 = p1 > 0.f ? p1 : 0.f;
            const float d1 = p1 > 0.f ? acc[nt][3] : 0.f;
            scr[s * SCRS + i0] = make_float2(h0, d0);
            scr[s * SCRS + i1] = make_float2(h1, d1);
        }
    }
    __syncthreads();

    // ---- layer 3 reduction
    {
        const int bl = tid & 127;               // sample
        const int q  = tid >> 7;                // quarter of i-reduction
        const float* w3n = w3g + n * HD;
        const float2* srow = (const float2*)(smem + OFF_SCR) + (size_t)bl * SCRS;
        float sv = 0.f, st = 0.f;
#pragma unroll 8
        for (int ii = q * 32; ii < q * 32 + 32; ii++) {
            const float wv = w3n[ii];
            const float2 h = srow[ii];
            sv = fmaf(wv, h.x, sv);
            st = fmaf(wv, h.y, st);
        }
        float* redv = (float*)(smem + OFF_RED);
        float* redt = redv + 512;
        redv[q * BT + bl] = sv;
        redt[q * BT + bl] = st;
    }
    __syncthreads();

    // ---- trig epilogue: 512 threads, (sample, output-kind) split; __sincosf
    {
        const int bl = tid & 127, kind = tid >> 7;
        const int jg = base + bl;
        if (jg < BHALF) {
            const float* redv = (const float*)(smem + OFF_RED);
            const float* redt = redv + 512;
            const float v = redv[bl] + redv[BT + bl] + redv[2 * BT + bl]
                          + redv[3 * BT + bl] + b3g[n];
            const float t = redt[bl] + redt[BT + bl] + redt[2 * BT + bl]
                          + redt[3 * BT + bl];
            const float bsq = v * v;
            const float dbv = 2.f * v * t;
            float a = sqrtag[n]; a = a * a;
            const size_t NL = (size_t)NCUR * LFULL;
            const size_t o  = (size_t)n * LFULL + jg;
            float s, c;
            __sincosf(alpha[jg], &s, &c);
            const bool mir = (jg < BHALF - 1);
            const int l = 2 * (BHALF - 1) - jg;
            float s2 = 0.f, c2 = 0.f;
            if (mir) __sincosf(alpha[l], &s2, &c2);
            const size_t o2 = (size_t)n * LFULL + l;
            switch (kind) {
                case 0:
                    out[o] = a * (c - 1.f);
                    if (mir) out[o2] = a * (c2 - 1.f);
                    break;
                case 1:
                    out[NL + o] = bsq * s;
                    if (mir) out[NL + o2] = bsq * s2;
                    break;
                case 2:
                    out[2 * NL + o] = -a * s;
                    if (mir) out[2 * NL + o2] = -a * s2;
                    break;
                default:
                    out[3 * NL + o] = fmaf(bsq, c, dbv * s);
                    if (mir) out[3 * NL + o2] = fmaf(bsq, c2, -dbv * s2);
            }
        }
    }
}

extern "C" void kernel_launch(void* const* d_in, const int* in_sizes, int n_in,
                              void* d_out, int out_size) {
    (void)in_sizes; (void)n_in; (void)out_size;
    const float* alpha  = (const float*)d_in[0];
    const float* w0     = (const float*)d_in[1];
    const float* w1     = (const float*)d_in[2];
    const float* w2     = (const float*)d_in[3];
    const float* w3     = (const float*)d_in[4];
    const float* b0     = (const float*)d_in[5];
    const float* b1     = (const float*)d_in[6];
    const float* b2     = (const float*)d_in[7];
    const float* b3     = (const float*)d_in[8];
    const float* sqrt_a = (const float*)d_in[9];
    float* out = (float*)d_out;

    split_w_kernel<<<(NCUR * HD * HD + 255) / 256, 256>>>(w1, w2);

    cudaFuncSetAttribute(sofa_kernel, cudaFuncAttributeMaxDynamicSharedMemorySize,
                         SMEM_BYTES);
    dim3 grid(NTILES, NCUR);   // (17, 128)
    sofa_kernel<<<grid, NTHREADS, SMEM_BYTES>>>(alpha, w0, w3,
                                                b0, b1, b2, b3, sqrt_a, out);
}

// round 14
// speedup vs baseline: 1.2196x; 1.2196x over previous
#include <cuda_runtime.h>
#include <cuda_bf16.h>
#include <math.h>
#include <stdint.h>

// SofaNetEllipse R13: 2 blocks/SM for cross-block phase overlap.
// 256 threads, BT=64 samples/block, grid (33,128). B smem only (69.6KB);
// W1/W2 pre-split bf16 hi/lo in global, fragments via LDG (latency hidden by
// co-resident block). Truncation-based hi/lo split; __sincosf tail.

typedef unsigned long long ull;

namespace {
constexpr int HD = 128, NCUR = 128, LFULL = 4097, BHALF = 2049, BT = 64;
constexpr int NTILES   = 33;             // 33*64 = 2112 >= 2049
constexpr int NTHREADS = 256;
constexpr int BKB = 272;                 // B k-row stride bytes (128 c-cols*2B + 16 pad)
constexpr int OFF_BHI = 0;
constexpr int OFF_BLO = OFF_BHI + HD * BKB;   // 34816
constexpr int OFF_SCR = 0;               // layer-3 scratch float2[s][i] aliases B
constexpr int SCRS = 129;                // float2 units -> 64*129*8 = 66048 < 69632
constexpr int OFF_RED = 69632;           // past B
constexpr int SMEM_BYTES = OFF_RED + 2048;    // 71680 -> 2 blocks/SM
}

// pre-split bf16 weights (written by prologue kernel each launch)
__device__ __nv_bfloat16 g_w1hi[NCUR * HD * HD];
__device__ __nv_bfloat16 g_w1lo[NCUR * HD * HD];
__device__ __nv_bfloat16 g_w2hi[NCUR * HD * HD];
__device__ __nv_bfloat16 g_w2lo[NCUR * HD * HD];

__device__ __forceinline__ uint32_t smem_u32(const void* p) {
    uint32_t a;
    asm("{ .reg .u64 t; cvta.to.shared.u64 t, %1; cvt.u32.u64 %0, t; }" : "=r"(a) : "l"(p));
    return a;
}
__device__ __forceinline__ void ldsm4t(uint32_t (&r)[4], uint32_t addr) {
    asm volatile("ldmatrix.sync.aligned.m8n8.x4.trans.shared.b16 {%0,%1,%2,%3}, [%4];"
                 : "=r"(r[0]), "=r"(r[1]), "=r"(r[2]), "=r"(r[3]) : "r"(addr));
}
__device__ __forceinline__ void stsm4(uint32_t addr, uint32_t r0, uint32_t r1,
                                      uint32_t r2, uint32_t r3) {
    asm volatile("stmatrix.sync.aligned.m8n8.x4.shared.b16 [%0], {%1,%2,%3,%4};"
                 :: "r"(addr), "r"(r0), "r"(r1), "r"(r2), "r"(r3) : "memory");
}
__device__ __forceinline__ void mma_bf16(float (&d)[4], const uint32_t (&a)[4],
                                         uint32_t b0, uint32_t b1) {
    asm volatile(
        "mma.sync.aligned.m16n8k16.row.col.f32.bf16.bf16.f32 "
        "{%0,%1,%2,%3}, {%4,%5,%6,%7}, {%8,%9}, {%0,%1,%2,%3};"
        : "+f"(d[0]), "+f"(d[1]), "+f"(d[2]), "+f"(d[3])
        : "r"(a[0]), "r"(a[1]), "r"(a[2]), "r"(a[3]), "r"(b0), "r"(b1));
}
// truncation split of pair (x,y): hi = upper 16 bits (exact residual), lo = rn(resid)
__device__ __forceinline__ void split2(float x, float y, uint32_t& hi, uint32_t& lo) {
    const uint32_t xb = __float_as_uint(x), yb = __float_as_uint(y);
    uint32_t h;
    asm("prmt.b32 %0, %1, %2, 0x7632;" : "=r"(h) : "r"(xb), "r"(yb));  // {x.hi16, y.hi16}
    hi = h;
    const float lx = x - __uint_as_float(xb & 0xFFFF0000u);
    const float ly = y - __uint_as_float(yb & 0xFFFF0000u);
    asm("cvt.rn.bf16x2.f32 %0, %2, %1;" : "=r"(lo) : "f"(lx), "f"(ly));
}

// ---- prologue: split fp32 W1/W2 into bf16 hi/lo (truncation) global buffers
__global__ void split_w_kernel(const float* __restrict__ w1, const float* __restrict__ w2) {
    const int idx = blockIdx.x * blockDim.x + threadIdx.x;
    if (idx < NCUR * HD * HD) {
        {
            const float v = w1[idx];
            const uint32_t vb = __float_as_uint(v) & 0xFFFF0000u;
            *(uint16_t*)&g_w1hi[idx] = (uint16_t)(vb >> 16);
            g_w1lo[idx] = __float2bfloat16(v - __uint_as_float(vb));
        }
        {
            const float v = w2[idx];
            const uint32_t vb = __float_as_uint(v) & 0xFFFF0000u;
            *(uint16_t*)&g_w2hi[idx] = (uint16_t)(vb >> 16);
            g_w2lo[idx] = __float2bfloat16(v - __uint_as_float(vb));
        }
    }
}

// One layer GEMM: 3-term bf16 (Whi*Hhi + Wlo*Hhi + Whi*Hlo), M-tile 16 (mt),
// N = 128 c-cols. W fragments via LDG (prefetched 1 k-step ahead); B from smem
// [k][c] via ldmatrix.trans (fragment layout verified in R10/R11).
__device__ __forceinline__ void gemm_layer_ldg(float (&acc)[16][4], uint32_t sb,
                                               const __nv_bfloat16* __restrict__ ghi,
                                               const __nv_bfloat16* __restrict__ glo,
                                               int mt, int lane) {
    const int row = 16 * mt + (lane >> 2);
    const int kc  = 2 * (lane & 3);
    const __nv_bfloat16* ph = ghi + row * HD + kc;
    const __nv_bfloat16* pl = glo + row * HD + kc;

    const int krow = (lane & 7) + (lane & 8);
    const int colb = (lane & 16) >> 1;            // c offset 0 or 8
    const uint32_t b_off = (uint32_t)(krow * BKB) + (uint32_t)(colb * 2);
    const uint32_t b_hi = sb + OFF_BHI + b_off;
    const uint32_t b_lo = sb + OFF_BLO + b_off;

    uint32_t cah[4], cal[4];
#pragma unroll
    for (int q = 0; q < 4; q++) {
        const int o = ((q & 1) ? 8 * HD : 0) + ((q & 2) ? 8 : 0);
        cah[q] = __ldg((const uint32_t*)(ph + o));
        cal[q] = __ldg((const uint32_t*)(pl + o));
    }

#pragma unroll
    for (int kk = 0; kk < 8; kk++) {
        uint32_t nah[4], nal[4];
        if (kk < 7) {
            const int kb = 16 * (kk + 1);
#pragma unroll
            for (int q = 0; q < 4; q++) {
                const int o = kb + ((q & 1) ? 8 * HD : 0) + ((q & 2) ? 8 : 0);
                nah[q] = __ldg((const uint32_t*)(ph + o));
                nal[q] = __ldg((const uint32_t*)(pl + o));
            }
        }
        const uint32_t kb_s = (uint32_t)kk * (16u * BKB);
#pragma unroll
        for (int g = 0; g < 4; g++) {
            const uint32_t go = kb_s + (uint32_t)(64 * g);   // +32 c-cols per group
            uint32_t bh0[4], bh1[4], bl0[4], bl1[4];
            ldsm4t(bh0, b_hi + go);
            ldsm4t(bh1, b_hi + go + 32u);                    // +16 c-cols
            ldsm4t(bl0, b_lo + go);
            ldsm4t(bl1, b_lo + go + 32u);
            mma_bf16(acc[4 * g + 0], cah, bh0[0], bh0[1]);
            mma_bf16(acc[4 * g + 1], cah, bh0[2], bh0[3]);
            mma_bf16(acc[4 * g + 2], cah, bh1[0], bh1[1]);
            mma_bf16(acc[4 * g + 3], cah, bh1[2], bh1[3]);
            mma_bf16(acc[4 * g + 0], cal, bh0[0], bh0[1]);
            mma_bf16(acc[4 * g + 1], cal, bh0[2], bh0[3]);
            mma_bf16(acc[4 * g + 2], cal, bh1[0], bh1[1]);
            mma_bf16(acc[4 * g + 3], cal, bh1[2], bh1[3]);
            mma_bf16(acc[4 * g + 0], cah, bl0[0], bl0[1]);
            mma_bf16(acc[4 * g + 1], cah, bl0[2], bl0[3]);
            mma_bf16(acc[4 * g + 2], cah, bl1[0], bl1[1]);
            mma_bf16(acc[4 * g + 3], cah, bl1[2], bl1[3]);
        }
        if (kk < 7) {
#pragma unroll
            for (int q = 0; q < 4; q++) { cah[q] = nah[q]; cal[q] = nal[q]; }
        }
    }
}

__global__ void __launch_bounds__(NTHREADS, 2)
sofa_kernel(const float* __restrict__ alpha,
            const float* __restrict__ w0g, const float* __restrict__ w3g,
            const float* __restrict__ b0g, const float* __restrict__ b1g,
            const float* __restrict__ b2g, const float* __restrict__ b3g,
            const float* __restrict__ sqrtag, float* __restrict__ out) {
    extern __shared__ char smem[];
    const uint32_t sb = smem_u32(smem);
    const int tid = threadIdx.x;
    const int wid = tid >> 5, lane = tid & 31;
    const int mt = wid;                             // warp = M-tile (0..7)
    const int g8 = lane >> 2, t4 = lane & 3;        // D frag coords
    const int n = blockIdx.y, tile = blockIdx.x, base = tile * BT;
    const size_t woff = (size_t)n * HD * HD;

    // ---- layer 0: B[k=j][c=2s|2s+1] = {h0, dh0}, STS.128 pairs
    {
        const float* w0n = w0g + n * HD;
        const float* b0n = b0g + n * HD;
#pragma unroll 1
        for (int it = 0; it < 4; it++) {
            const int task = tid + 256 * it;        // 0..1023 = (j, 8-sample group)
            const int j = task >> 3, sgl = task & 7;
            const float w = w0n[j], bb = b0n[j];
            uint32_t hw[8], lw[8];
#pragma unroll
            for (int q = 0; q < 8; q++) {
                const float a = alpha[base + sgl * 8 + q];  // <= 2111+.. < 4097
                const float pre = fmaf(w, a, bb);
                const float h = pre > 0.f ? pre : 0.f;
                const float d = pre > 0.f ? w : 0.f;
                split2(h, d, hw[q], lw[q]);
            }
            const int rowb = j * BKB + sgl * 32;            // c0 = 16*sgl
            *(uint4*)(smem + OFF_BHI + rowb)      = make_uint4(hw[0], hw[1], hw[2], hw[3]);
            *(uint4*)(smem + OFF_BHI + rowb + 16) = make_uint4(hw[4], hw[5], hw[6], hw[7]);
            *(uint4*)(smem + OFF_BLO + rowb)      = make_uint4(lw[0], lw[1], lw[2], lw[3]);
            *(uint4*)(smem + OFF_BLO + rowb + 16) = make_uint4(lw[4], lw[5], lw[6], lw[7]);
        }
    }
    __syncthreads();

    // ---- layer 1 GEMM
    float acc[16][4];
#pragma unroll
    for (int a_ = 0; a_ < 16; a_++)
#pragma unroll
        for (int b_ = 0; b_ < 4; b_++) acc[a_][b_] = 0.f;
    gemm_layer_ldg(acc, sb, g_w1hi + woff, g_w1lo + woff, mt, lane);
    __syncthreads();    // all B reads done before overwrite

    // ---- layer-1 epilogue via stmatrix back into B
    {
        const int i0 = 16 * mt + g8;
        const float bias0 = b1g[n * HD + i0];
        const float bias1 = b1g[n * HD + i0 + 8];
        const int h8 = (lane >> 3) & 1, v8 = (lane >> 4) & 1, lr = lane & 7;
        const uint32_t st_hi = sb + OFF_BHI
            + (uint32_t)((16 * mt + 8 * h8 + lr) * BKB) + (uint32_t)((8 * v8) * 2);
        const uint32_t st_lo = st_hi + (uint32_t)(OFF_BLO - OFF_BHI);
#pragma unroll
        for (int v = 0; v < 16; v += 2) {
            uint32_t h0, h1, h2, h3, l0, l1, l2, l3;
            {
                const float p = acc[v][0] + bias0;
                split2(p > 0.f ? p : 0.f, p > 0.f ? acc[v][1] : 0.f, h0, l0);
            }
            {
                const float p = acc[v][2] + bias1;
                split2(p > 0.f ? p : 0.f, p > 0.f ? acc[v][3] : 0.f, h1, l1);
            }
            {
                const float p = acc[v + 1][0] + bias0;
                split2(p > 0.f ? p : 0.f, p > 0.f ? acc[v + 1][1] : 0.f, h2, l2);
            }
            {
                const float p = acc[v + 1][2] + bias1;
                split2(p > 0.f ? p : 0.f, p > 0.f ? acc[v + 1][3] : 0.f, h3, l3);
            }
            stsm4(st_hi + (uint32_t)(v * 16), h0, h1, h2, h3);
            stsm4(st_lo + (uint32_t)(v * 16), l0, l1, l2, l3);
        }
    }
    __syncthreads();

    // ---- layer 2 GEMM
#pragma unroll
    for (int a_ = 0; a_ < 16; a_++)
#pragma unroll
        for (int b_ = 0; b_ < 4; b_++) acc[a_][b_] = 0.f;
    gemm_layer_ldg(acc, sb, g_w2hi + woff, g_w2lo + woff, mt, lane);
    __syncthreads();    // B reads done; scratch aliases B

    // ---- layer-2 epilogue: fp32 {h2, dh2} -> scratch [s][i]
    {
        float2* scr = (float2*)(smem + OFF_SCR);
        const int i0 = 16 * mt + g8, i1 = i0 + 8;
        const float bias0 = b2g[n * HD + i0];
        const float bias1 = b2g[n * HD + i1];
#pragma unroll
        for (int nt = 0; nt < 16; nt++) {
            const int s = 4 * nt + t4;                  // 0..63
            const float p0 = acc[nt][0] + bias0;
            const float h0 = p0 > 0.f ? p0 : 0.f;
            const float d0 = p0 > 0.f ? acc[nt][1] : 0.f;
            const float p1 = acc[nt][2] + bias1;
            const float h1 = p1 > 0.f ? p1 : 0.f;
            const float d1 = p1 > 0.f ? acc[nt][3] : 0.f;
            scr[s * SCRS + i0] = make_float2(h0, d0);
            scr[s * SCRS + i1] = make_float2(h1, d1);
        }
    }
    __syncthreads();

    // ---- layer 3 reduction: 256 threads = 64 samples x 4 quarters
    {
        const int bl = tid & 63;
        const int q  = tid >> 6;
        const float* w3n = w3g + n * HD;
        const float2* srow = (const float2*)(smem + OFF_SCR) + (size_t)bl * SCRS;
        float sv = 0.f, st = 0.f;
#pragma unroll 8
        for (int ii = q * 32; ii < q * 32 + 32; ii++) {
            const float wv = w3n[ii];
            const float2 h = srow[ii];
            sv = fmaf(wv, h.x, sv);
            st = fmaf(wv, h.y, st);
        }
        float* redv = (float*)(smem + OFF_RED);
        float* redt = redv + 256;
        redv[q * 64 + bl] = sv;
        redt[q * 64 + bl] = st;
    }
    __syncthreads();

    // ---- trig epilogue: 256 threads = 64 samples x 4 output kinds; __sincosf
    {
        const int bl = tid & 63, kind = tid >> 6;
        const int jg = base + bl;
        if (jg < BHALF) {
            const float* redv = (const float*)(smem + OFF_RED);
            const float* redt = redv + 256;
            const float v = redv[bl] + redv[64 + bl] + redv[128 + bl]
                          + redv[192 + bl] + b3g[n];
            const float t = redt[bl] + redt[64 + bl] + redt[128 + bl]
                          + redt[192 + bl];
            const float bsq = v * v;
            const float dbv = 2.f * v * t;
            float a = sqrtag[n]; a = a * a;
            const size_t NL = (size_t)NCUR * LFULL;
            const size_t o  = (size_t)n * LFULL + jg;
            float s, c;
            __sincosf(alpha[jg], &s, &c);
            const bool mir = (jg < BHALF - 1);
            const int l = 2 * (BHALF - 1) - jg;
            float s2 = 0.f, c2 = 0.f;
            if (mir) __sincosf(alpha[l], &s2, &c2);
            const size_t o2 = (size_t)n * LFULL + l;
            switch (kind) {
                case 0:
                    out[o] = a * (c - 1.f);
                    if (mir) out[o2] = a * (c2 - 1.f);
                    break;
                case 1:
                    out[NL + o] = bsq * s;
                    if (mir) out[NL + o2] = bsq * s2;
                    break;
                case 2:
                    out[2 * NL + o] = -a * s;
                    if (mir) out[2 * NL + o2] = -a * s2;
                    break;
                default:
                    out[3 * NL + o] = fmaf(bsq, c, dbv * s);
                    if (mir) out[3 * NL + o2] = fmaf(bsq, c2, -dbv * s2);
            }
        }
    }
}

extern "C" void kernel_launch(void* const* d_in, const int* in_sizes, int n_in,
                              void* d_out, int out_size) {
    (void)in_sizes; (void)n_in; (void)out_size;
    const float* alpha  = (const float*)d_in[0];
    const float* w0     = (const float*)d_in[1];
    const float* w1     = (const float*)d_in[2];
    const float* w2     = (const float*)d_in[3];
    const float* w3     = (const float*)d_in[4];
    const float* b0     = (const float*)d_in[5];
    const float* b1     = (const float*)d_in[6];
    const float* b2     = (const float*)d_in[7];
    const float* b3     = (const float*)d_in[8];
    const float* sqrt_a = (const float*)d_in[9];
    float* out = (float*)d_out;

    split_w_kernel<<<(NCUR * HD * HD + 255) / 256, 256>>>(w1, w2);

    cudaFuncSetAttribute(sofa_kernel, cudaFuncAttributeMaxDynamicSharedMemorySize,
                         SMEM_BYTES);
    dim3 grid(NTILES, NCUR);   // (33, 128)
    sofa_kernel<<<grid, NTHREADS, SMEM_BYTES>>>(alpha, w0, w3,
                                                b0, b1, b2, b3, sqrt_a, out);
}

// round 15
// speedup vs baseline: 1.5959x; 1.3085x over previous
#include <cuda_runtime.h>
#include <cuda_bf16.h>
#include <math.h>
#include <stdint.h>

// SofaNetEllipse R14: cut L1tex traffic (92.3% -> target ~55%).
//  - W pre-swizzled to MMA fragment order in prologue -> one LDG.128 per
//    (tile,kk,hi/lo) instead of 8 scattered LDG.32.
//  - Warp tile 32x64 (4 M-tiles x 2 N-halves): B fragments reused across 2
//    M-tiles in registers -> B LDSM traffic halved.
// Keeps R13's 2-blocks/SM (BT=64, 256 thr, 71.7KB smem), truncation split,
// __sincosf tail.

typedef unsigned long long ull;

namespace {
constexpr int HD = 128, NCUR = 128, LFULL = 4097, BHALF = 2049, BT = 64;
constexpr int NTILES   = 33;             // 33*64 = 2112 >= 2049
constexpr int NTHREADS = 256;
constexpr int BKB = 272;                 // B k-row stride bytes (128 c-cols*2B + 16 pad)
constexpr int OFF_BHI = 0;
constexpr int OFF_BLO = OFF_BHI + HD * BKB;   // 34816
constexpr int OFF_SCR = 0;               // layer-3 scratch float2[s][i] aliases B
constexpr int SCRS = 129;                // float2 units -> 64*129*8 = 66048 < 69632
constexpr int OFF_RED = 69632;           // past B
constexpr int SMEM_BYTES = OFF_RED + 2048;    // 71680 -> 2 blocks/SM
constexpr int WPC = 8192;                // fragment-order words per curve (128*128/2)
}

// W1/W2 in bf16 hi/lo, MMA-fragment order:
// word[(n*8 + mtile)*8*32*4 ... ] = ((n*8+mt)*8 + kk)*128 + lane*4 + q
// where q encodes (row+8*(q&1), k+8*(q>>1)), word = {bf16(k), bf16(k+1)}.
__device__ uint32_t g_w1hi[NCUR * WPC];
__device__ uint32_t g_w1lo[NCUR * WPC];
__device__ uint32_t g_w2hi[NCUR * WPC];
__device__ uint32_t g_w2lo[NCUR * WPC];

__device__ __forceinline__ uint32_t smem_u32(const void* p) {
    uint32_t a;
    asm("{ .reg .u64 t; cvta.to.shared.u64 t, %1; cvt.u32.u64 %0, t; }" : "=r"(a) : "l"(p));
    return a;
}
__device__ __forceinline__ void ldsm4t(uint32_t (&r)[4], uint32_t addr) {
    asm volatile("ldmatrix.sync.aligned.m8n8.x4.trans.shared.b16 {%0,%1,%2,%3}, [%4];"
                 : "=r"(r[0]), "=r"(r[1]), "=r"(r[2]), "=r"(r[3]) : "r"(addr));
}
__device__ __forceinline__ void stsm4(uint32_t addr, uint32_t r0, uint32_t r1,
                                      uint32_t r2, uint32_t r3) {
    asm volatile("stmatrix.sync.aligned.m8n8.x4.shared.b16 [%0], {%1,%2,%3,%4};"
                 :: "r"(addr), "r"(r0), "r"(r1), "r"(r2), "r"(r3) : "memory");
}
__device__ __forceinline__ void mma_bf16(float (&d)[4], const uint32_t* a,
                                         uint32_t b0, uint32_t b1) {
    asm volatile(
        "mma.sync.aligned.m16n8k16.row.col.f32.bf16.bf16.f32 "
        "{%0,%1,%2,%3}, {%4,%5,%6,%7}, {%8,%9}, {%0,%1,%2,%3};"
        : "+f"(d[0]), "+f"(d[1]), "+f"(d[2]), "+f"(d[3])
        : "r"(a[0]), "r"(a[1]), "r"(a[2]), "r"(a[3]), "r"(b0), "r"(b1));
}
// truncation split of pair (x,y): hi = upper 16 bits, lo = rn(residual)
__device__ __forceinline__ void split2(float x, float y, uint32_t& hi, uint32_t& lo) {
    const uint32_t xb = __float_as_uint(x), yb = __float_as_uint(y);
    uint32_t h;
    asm("prmt.b32 %0, %1, %2, 0x7632;" : "=r"(h) : "r"(xb), "r"(yb));  // {x.hi16, y.hi16}
    hi = h;
    const float lx = x - __uint_as_float(xb & 0xFFFF0000u);
    const float ly = y - __uint_as_float(yb & 0xFFFF0000u);
    asm("cvt.rn.bf16x2.f32 %0, %2, %1;" : "=r"(lo) : "f"(lx), "f"(ly));
}

// ---- prologue: fp32 W1/W2 -> bf16 hi/lo in fragment order
__global__ void split_w_kernel(const float* __restrict__ w1, const float* __restrict__ w2) {
    const int idx = blockIdx.x * blockDim.x + threadIdx.x;      // word index
    if (idx >= NCUR * WPC) return;
    const int n = idx >> 13, r = idx & (WPC - 1);
    const int mt = r >> 10, kk = (r >> 7) & 7, lane = (r >> 2) & 31, q = r & 3;
    const int i  = 16 * mt + (lane >> 2) + 8 * (q & 1);
    const int k0 = 16 * kk + 2 * (lane & 3) + 8 * (q >> 1);
    const size_t src = ((size_t)n * HD + i) * HD + k0;
    {
        uint32_t hi, lo;
        split2(w1[src], w1[src + 1], hi, lo);
        g_w1hi[idx] = hi; g_w1lo[idx] = lo;
    }
    {
        uint32_t hi, lo;
        split2(w2[src], w2[src + 1], hi, lo);
        g_w2hi[idx] = hi; g_w2lo[idx] = lo;
    }
}

// One layer GEMM: 3-term bf16 (Whi*Hhi + Wlo*Hhi + Whi*Hlo).
// Warp tile 32x64: M-tiles t=0,1 (rows 32mq+16t..+15), c-cols 64nh..+63.
// A fragments: coalesced LDG.128 from fragment-order globals.
// B: smem [k][c] via ldmatrix.trans; each B frag reused by both M-tiles.
__device__ __forceinline__ void gemm_layer(float (&acc)[2][8][4], uint32_t sb,
                                           const uint4* __restrict__ ghi,
                                           const uint4* __restrict__ glo,
                                           int mq, int nh, int lane) {
    const int krow = (lane & 7) + (lane & 8);
    const uint32_t b_off = (uint32_t)(krow * BKB)
                         + (uint32_t)(128 * nh) + (uint32_t)((lane & 16));  // +16B if lane>=16
    const uint32_t b_hi = sb + OFF_BHI + b_off;
    const uint32_t b_lo = sb + OFF_BLO + b_off;
    const int tb0 = 2 * mq * 8;                   // tile block (t=0), +8 for t=1

#pragma unroll
    for (int kk = 0; kk < 8; kk++) {
        uint4 cah[2], cal[2];
        cah[0] = __ldg(ghi + (tb0 + kk) * 32 + lane);
        cah[1] = __ldg(ghi + (tb0 + 8 + kk) * 32 + lane);
        cal[0] = __ldg(glo + (tb0 + kk) * 32 + lane);
        cal[1] = __ldg(glo + (tb0 + 8 + kk) * 32 + lane);
        const uint32_t kb = (uint32_t)kk * (16u * BKB);
#pragma unroll
        for (int g = 0; g < 2; g++) {
            const uint32_t go = kb + 64u * g;             // +32 c-cols per group
            uint32_t bh0[4], bh1[4], bl0[4], bl1[4];
            ldsm4t(bh0, b_hi + go);
            ldsm4t(bh1, b_hi + go + 32u);                 // +16 c-cols
            ldsm4t(bl0, b_lo + go);
            ldsm4t(bl1, b_lo + go + 32u);
#pragma unroll
            for (int t = 0; t < 2; t++) {
                const uint32_t* ah = (const uint32_t*)&cah[t];
                const uint32_t* al = (const uint32_t*)&cal[t];
                float (*ac)[4] = acc[t];
                mma_bf16(ac[4 * g + 0], ah, bh0[0], bh0[1]);
                mma_bf16(ac[4 * g + 1], ah, bh0[2], bh0[3]);
                mma_bf16(ac[4 * g + 2], ah, bh1[0], bh1[1]);
                mma_bf16(ac[4 * g + 3], ah, bh1[2], bh1[3]);
                mma_bf16(ac[4 * g + 0], al, bh0[0], bh0[1]);
                mma_bf16(ac[4 * g + 1], al, bh0[2], bh0[3]);
                mma_bf16(ac[4 * g + 2], al, bh1[0], bh1[1]);
                mma_bf16(ac[4 * g + 3], al, bh1[2], bh1[3]);
                mma_bf16(ac[4 * g + 0], ah, bl0[0], bl0[1]);
                mma_bf16(ac[4 * g + 1], ah, bl0[2], bl0[3]);
                mma_bf16(ac[4 * g + 2], ah, bl1[0], bl1[1]);
                mma_bf16(ac[4 * g + 3], ah, bl1[2], bl1[3]);
            }
        }
    }
}

__global__ void __launch_bounds__(NTHREADS, 2)
sofa_kernel(const float* __restrict__ alpha,
            const float* __restrict__ w0g, const float* __restrict__ w3g,
            const float* __restrict__ b0g, const float* __restrict__ b1g,
            const float* __restrict__ b2g, const float* __restrict__ b3g,
            const float* __restrict__ sqrtag, float* __restrict__ out) {
    extern __shared__ char smem[];
    const uint32_t sb = smem_u32(smem);
    const int tid = threadIdx.x;
    const int wid = tid >> 5, lane = tid & 31;
    const int mq = wid & 3, nh = wid >> 2;          // warp = (32-row M-tile, 64-col N-half)
    const int g8 = lane >> 2, t4 = lane & 3;        // D frag coords
    const int n = blockIdx.y, tile = blockIdx.x, base = tile * BT;
    const size_t woff = (size_t)n * WPC;

    // ---- layer 0: B[k=j][c=2s|2s+1] = {h0, dh0}, STS.128 pairs
    {
        const float* w0n = w0g + n * HD;
        const float* b0n = b0g + n * HD;
#pragma unroll 1
        for (int it = 0; it < 4; it++) {
            const int task = tid + 256 * it;        // 0..1023 = (j, 8-sample group)
            const int j = task >> 3, sgl = task & 7;
            const float w = w0n[j], bb = b0n[j];
            uint32_t hw[8], lw[8];
#pragma unroll
            for (int q = 0; q < 8; q++) {
                const float a = alpha[base + sgl * 8 + q];  // < 4097
                const float pre = fmaf(w, a, bb);
                const float h = pre > 0.f ? pre : 0.f;
                const float d = pre > 0.f ? w : 0.f;
                split2(h, d, hw[q], lw[q]);
            }
            const int rowb = j * BKB + sgl * 32;
            *(uint4*)(smem + OFF_BHI + rowb)      = make_uint4(hw[0], hw[1], hw[2], hw[3]);
            *(uint4*)(smem + OFF_BHI + rowb + 16) = make_uint4(hw[4], hw[5], hw[6], hw[7]);
            *(uint4*)(smem + OFF_BLO + rowb)      = make_uint4(lw[0], lw[1], lw[2], lw[3]);
            *(uint4*)(smem + OFF_BLO + rowb + 16) = make_uint4(lw[4], lw[5], lw[6], lw[7]);
        }
    }
    __syncthreads();

    // ---- layer 1 GEMM
    float acc[2][8][4];
#pragma unroll
    for (int t = 0; t < 2; t++)
#pragma unroll
        for (int a_ = 0; a_ < 8; a_++)
#pragma unroll
            for (int b_ = 0; b_ < 4; b_++) acc[t][a_][b_] = 0.f;
    gemm_layer(acc, sb, (const uint4*)(g_w1hi + woff), (const uint4*)(g_w1lo + woff),
               mq, nh, lane);
    __syncthreads();    // all B reads done before overwrite

    // ---- layer-1 epilogue via stmatrix back into B
    {
        const int h8 = (lane >> 3) & 1, v8 = (lane >> 4) & 1, lr = lane & 7;
#pragma unroll
        for (int t = 0; t < 2; t++) {
            const int i0 = 32 * mq + 16 * t + g8;
            const float bias0 = b1g[n * HD + i0];
            const float bias1 = b1g[n * HD + i0 + 8];
            const uint32_t st_hi = sb + OFF_BHI
                + (uint32_t)((32 * mq + 16 * t + 8 * h8 + lr) * BKB)
                + (uint32_t)((64 * nh + 8 * v8) * 2);
            const uint32_t st_lo = st_hi + (uint32_t)(OFF_BLO - OFF_BHI);
#pragma unroll
            for (int v = 0; v < 8; v += 2) {
                uint32_t h0, h1, h2, h3, l0, l1, l2, l3;
                {
                    const float p = acc[t][v][0] + bias0;
                    split2(p > 0.f ? p : 0.f, p > 0.f ? acc[t][v][1] : 0.f, h0, l0);
                }
                {
                    const float p = acc[t][v][2] + bias1;
                    split2(p > 0.f ? p : 0.f, p > 0.f ? acc[t][v][3] : 0.f, h1, l1);
                }
                {
                    const float p = acc[t][v + 1][0] + bias0;
                    split2(p > 0.f ? p : 0.f, p > 0.f ? acc[t][v + 1][1] : 0.f, h2, l2);
                }
                {
                    const float p = acc[t][v + 1][2] + bias1;
                    split2(p > 0.f ? p : 0.f, p > 0.f ? acc[t][v + 1][3] : 0.f, h3, l3);
                }
                stsm4(st_hi + (uint32_t)(v * 16), h0, h1, h2, h3);
                stsm4(st_lo + (uint32_t)(v * 16), l0, l1, l2, l3);
            }
        }
    }
    __syncthreads();

    // ---- layer 2 GEMM
#pragma unroll
    for (int t = 0; t < 2; t++)
#pragma unroll
        for (int a_ = 0; a_ < 8; a_++)
#pragma unroll
            for (int b_ = 0; b_ < 4; b_++) acc[t][a_][b_] = 0.f;
    gemm_layer(acc, sb, (const uint4*)(g_w2hi + woff), (const uint4*)(g_w2lo + woff),
               mq, nh, lane);
    __syncthreads();    // B reads done; scratch aliases B

    // ---- layer-2 epilogue: fp32 {h2, dh2} -> scratch [s][i]
    {
        float2* scr = (float2*)(smem + OFF_SCR);
#pragma unroll
        for (int t = 0; t < 2; t++) {
            const int i0 = 32 * mq + 16 * t + g8, i1 = i0 + 8;
            const float bias0 = b2g[n * HD + i0];
            const float bias1 = b2g[n * HD + i1];
#pragma unroll
            for (int nt = 0; nt < 8; nt++) {
                const int s = 32 * nh + 4 * nt + t4;        // 0..63
                const float p0 = acc[t][nt][0] + bias0;
                const float h0 = p0 > 0.f ? p0 : 0.f;
                const float d0 = p0 > 0.f ? acc[t][nt][1] : 0.f;
                const float p1 = acc[t][nt][2] + bias1;
                const float h1 = p1 > 0.f ? p1 : 0.f;
                const float d1 = p1 > 0.f ? acc[t][nt][3] : 0.f;
                scr[s * SCRS + i0] = make_float2(h0, d0);
                scr[s * SCRS + i1] = make_float2(h1, d1);
            }
        }
    }
    __syncthreads();

    // ---- layer 3 reduction: 256 threads = 64 samples x 4 quarters
    {
        const int bl = tid & 63;
        const int q  = tid >> 6;
        const float* w3n = w3g + n * HD;
        const float2* srow = (const float2*)(smem + OFF_SCR) + (size_t)bl * SCRS;
        float sv = 0.f, st = 0.f;
#pragma unroll 8
        for (int ii = q * 32; ii < q * 32 + 32; ii++) {
            const float wv = w3n[ii];
            const float2 h = srow[ii];
            sv = fmaf(wv, h.x, sv);
            st = fmaf(wv, h.y, st);
        }
        float* redv = (float*)(smem + OFF_RED);
        float* redt = redv + 256;
        redv[q * 64 + bl] = sv;
        redt[q * 64 + bl] = st;
    }
    __syncthreads();

    // ---- trig epilogue: 256 threads = 64 samples x 4 output kinds; __sincosf
    {
        const int bl = tid & 63, kind = tid >> 6;
        const int jg = base + bl;
        if (jg < BHALF) {
            const float* redv = (const float*)(smem + OFF_RED);
            const float* redt = redv + 256;
            const float v = redv[bl] + redv[64 + bl] + redv[128 + bl]
                          + redv[192 + bl] + b3g[n];
            const float t = redt[bl] + redt[64 + bl] + redt[128 + bl]
                          + redt[192 + bl];
            const float bsq = v * v;
            const float dbv = 2.f * v * t;
            float a = sqrtag[n]; a = a * a;
            const size_t NL = (size_t)NCUR * LFULL;
            const size_t o  = (size_t)n * LFULL + jg;
            float s, c;
            __sincosf(alpha[jg], &s, &c);
            const bool mir = (jg < BHALF - 1);
            const int l = 2 * (BHALF - 1) - jg;
            float s2 = 0.f, c2 = 0.f;
            if (mir) __sincosf(alpha[l], &s2, &c2);
            const size_t o2 = (size_t)n * LFULL + l;
            switch (kind) {
                case 0:
                    out[o] = a * (c - 1.f);
                    if (mir) out[o2] = a * (c2 - 1.f);
                    break;
                case 1:
                    out[NL + o] = bsq * s;
                    if (mir) out[NL + o2] = bsq * s2;
                    break;
                case 2:
                    out[2 * NL + o] = -a * s;
                    if (mir) out[2 * NL + o2] = -a * s2;
                    break;
                default:
                    out[3 * NL + o] = fmaf(bsq, c, dbv * s);
                    if (mir) out[3 * NL + o2] = fmaf(bsq, c2, -dbv * s2);
            }
        }
    }
}

extern "C" void kernel_launch(void* const* d_in, const int* in_sizes, int n_in,
                              void* d_out, int out_size) {
    (void)in_sizes; (void)n_in; (void)out_size;
    const float* alpha  = (const float*)d_in[0];
    const float* w0     = (const float*)d_in[1];
    const float* w1     = (const float*)d_in[2];
    const float* w2     = (const float*)d_in[3];
    const float* w3     = (const float*)d_in[4];
    const float* b0     = (const float*)d_in[5];
    const float* b1     = (const float*)d_in[6];
    const float* b2     = (const float*)d_in[7];
    const float* b3     = (const float*)d_in[8];
    const float* sqrt_a = (const float*)d_in[9];
    float* out = (float*)d_out;

    split_w_kernel<<<(NCUR * WPC + 255) / 256, 256>>>(w1, w2);

    cudaFuncSetAttribute(sofa_kernel, cudaFuncAttributeMaxDynamicSharedMemorySize,
                         SMEM_BYTES);
    dim3 grid(NTILES, NCUR);   // (33, 128)
    sofa_kernel<<<grid, NTHREADS, SMEM_BYTES>>>(alpha, w0, w3,
                                                b0, b1, b2, b3, sqrt_a, out);
}

// round 16
// speedup vs baseline: 1.8004x; 1.1281x over previous
#include <cuda_runtime.h>
#include <cuda_bf16.h>
#include <math.h>
#include <stdint.h>

// SofaNetEllipse R15: R14 + layer-3 fused into the GEMM2 epilogue.
// The layer-3 dot is computed straight from MMA acc fragments (bias+relu+mask
// in regs, w3 multiply, shfl-reduce over the 8 g8-lanes, 2KB red array) --
// deletes the fp32 scratch round-trip, one __syncthreads, and the whole
// layer-3 LDS reduction phase. Everything else identical to R14
// (2 blocks/SM, fragment-order W via LDG.128, 32x64 warp tiles, trunc split).

typedef unsigned long long ull;

namespace {
constexpr int HD = 128, NCUR = 128, LFULL = 4097, BHALF = 2049, BT = 64;
constexpr int NTILES   = 33;             // 33*64 = 2112 >= 2049
constexpr int NTHREADS = 256;
constexpr int BKB = 272;                 // B k-row stride bytes (128 c-cols*2B + 16 pad)
constexpr int OFF_BHI = 0;
constexpr int OFF_BLO = OFF_BHI + HD * BKB;   // 34816
constexpr int OFF_RED = 69632;           // past B: 2KB red arrays
constexpr int SMEM_BYTES = OFF_RED + 2048;    // 71680 -> 2 blocks/SM
constexpr int WPC = 8192;                // fragment-order words per curve (128*128/2)
}

// W1/W2 in bf16 hi/lo, MMA-fragment order:
// word idx = ((n*8+mt)*8 + kk)*128 + lane*4 + q,
// q encodes (row+8*(q&1), k+8*(q>>1)), word = {bf16(k), bf16(k+1)}.
__device__ uint32_t g_w1hi[NCUR * WPC];
__device__ uint32_t g_w1lo[NCUR * WPC];
__device__ uint32_t g_w2hi[NCUR * WPC];
__device__ uint32_t g_w2lo[NCUR * WPC];

__device__ __forceinline__ uint32_t smem_u32(const void* p) {
    uint32_t a;
    asm("{ .reg .u64 t; cvta.to.shared.u64 t, %1; cvt.u32.u64 %0, t; }" : "=r"(a) : "l"(p));
    return a;
}
__device__ __forceinline__ void ldsm4t(uint32_t (&r)[4], uint32_t addr) {
    asm volatile("ldmatrix.sync.aligned.m8n8.x4.trans.shared.b16 {%0,%1,%2,%3}, [%4];"
                 : "=r"(r[0]), "=r"(r[1]), "=r"(r[2]), "=r"(r[3]) : "r"(addr));
}
__device__ __forceinline__ void stsm4(uint32_t addr, uint32_t r0, uint32_t r1,
                                      uint32_t r2, uint32_t r3) {
    asm volatile("stmatrix.sync.aligned.m8n8.x4.shared.b16 [%0], {%1,%2,%3,%4};"
                 :: "r"(addr), "r"(r0), "r"(r1), "r"(r2), "r"(r3) : "memory");
}
__device__ __forceinline__ void mma_bf16(float (&d)[4], const uint32_t* a,
                                         uint32_t b0, uint32_t b1) {
    asm volatile(
        "mma.sync.aligned.m16n8k16.row.col.f32.bf16.bf16.f32 "
        "{%0,%1,%2,%3}, {%4,%5,%6,%7}, {%8,%9}, {%0,%1,%2,%3};"
        : "+f"(d[0]), "+f"(d[1]), "+f"(d[2]), "+f"(d[3])
        : "r"(a[0]), "r"(a[1]), "r"(a[2]), "r"(a[3]), "r"(b0), "r"(b1));
}
// truncation split of pair (x,y): hi = upper 16 bits, lo = rn(residual)
__device__ __forceinline__ void split2(float x, float y, uint32_t& hi, uint32_t& lo) {
    const uint32_t xb = __float_as_uint(x), yb = __float_as_uint(y);
    uint32_t h;
    asm("prmt.b32 %0, %1, %2, 0x7632;" : "=r"(h) : "r"(xb), "r"(yb));  // {x.hi16, y.hi16}
    hi = h;
    const float lx = x - __uint_as_float(xb & 0xFFFF0000u);
    const float ly = y - __uint_as_float(yb & 0xFFFF0000u);
    asm("cvt.rn.bf16x2.f32 %0, %2, %1;" : "=r"(lo) : "f"(lx), "f"(ly));
}

// ---- prologue: fp32 W1/W2 -> bf16 hi/lo in fragment order
__global__ void split_w_kernel(const float* __restrict__ w1, const float* __restrict__ w2) {
    const int idx = blockIdx.x * blockDim.x + threadIdx.x;      // word index
    if (idx >= NCUR * WPC) return;
    const int n = idx >> 13, r = idx & (WPC - 1);
    const int mt = r >> 10, kk = (r >> 7) & 7, lane = (r >> 2) & 31, q = r & 3;
    const int i  = 16 * mt + (lane >> 2) + 8 * (q & 1);
    const int k0 = 16 * kk + 2 * (lane & 3) + 8 * (q >> 1);
    const size_t src = ((size_t)n * HD + i) * HD + k0;
    {
        uint32_t hi, lo;
        split2(w1[src], w1[src + 1], hi, lo);
        g_w1hi[idx] = hi; g_w1lo[idx] = lo;
    }
    {
        uint32_t hi, lo;
        split2(w2[src], w2[src + 1], hi, lo);
        g_w2hi[idx] = hi; g_w2lo[idx] = lo;
    }
}

// One layer GEMM: 3-term bf16 (Whi*Hhi + Wlo*Hhi + Whi*Hlo).
// Warp tile 32x64: M-tiles t=0,1 (rows 32mq+16t..+15), c-cols 64nh..+63.
// A fragments via coalesced LDG.128 (fragment order); B via ldmatrix.trans,
// each B frag reused by both M-tiles.
__device__ __forceinline__ void gemm_layer(float (&acc)[2][8][4], uint32_t sb,
                                           const uint4* __restrict__ ghi,
                                           const uint4* __restrict__ glo,
                                           int mq, int nh, int lane) {
    const int krow = (lane & 7) + (lane & 8);
    const uint32_t b_off = (uint32_t)(krow * BKB)
                         + (uint32_t)(128 * nh) + (uint32_t)((lane & 16));
    const uint32_t b_hi = sb + OFF_BHI + b_off;
    const uint32_t b_lo = sb + OFF_BLO + b_off;
    const int tb0 = 2 * mq * 8;                   // tile block (t=0), +8 for t=1

#pragma unroll
    for (int kk = 0; kk < 8; kk++) {
        uint4 cah[2], cal[2];
        cah[0] = __ldg(ghi + (tb0 + kk) * 32 + lane);
        cah[1] = __ldg(ghi + (tb0 + 8 + kk) * 32 + lane);
        cal[0] = __ldg(glo + (tb0 + kk) * 32 + lane);
        cal[1] = __ldg(glo + (tb0 + 8 + kk) * 32 + lane);
        const uint32_t kb = (uint32_t)kk * (16u * BKB);
#pragma unroll
        for (int g = 0; g < 2; g++) {
            const uint32_t go = kb + 64u * g;             // +32 c-cols per group
            uint32_t bh0[4], bh1[4], bl0[4], bl1[4];
            ldsm4t(bh0, b_hi + go);
            ldsm4t(bh1, b_hi + go + 32u);                 // +16 c-cols
            ldsm4t(bl0, b_lo + go);
            ldsm4t(bl1, b_lo + go + 32u);
#pragma unroll
            for (int t = 0; t < 2; t++) {
                const uint32_t* ah = (const uint32_t*)&cah[t];
                const uint32_t* al = (const uint32_t*)&cal[t];
                float (*ac)[4] = acc[t];
                mma_bf16(ac[4 * g + 0], ah, bh0[0], bh0[1]);
                mma_bf16(ac[4 * g + 1], ah, bh0[2], bh0[3]);
                mma_bf16(ac[4 * g + 2], ah, bh1[0], bh1[1]);
                mma_bf16(ac[4 * g + 3], ah, bh1[2], bh1[3]);
                mma_bf16(ac[4 * g + 0], al, bh0[0], bh0[1]);
                mma_bf16(ac[4 * g + 1], al, bh0[2], bh0[3]);
                mma_bf16(ac[4 * g + 2], al, bh1[0], bh1[1]);
                mma_bf16(ac[4 * g + 3], al, bh1[2], bh1[3]);
                mma_bf16(ac[4 * g + 0], ah, bl0[0], bl0[1]);
                mma_bf16(ac[4 * g + 1], ah, bl0[2], bl0[3]);
                mma_bf16(ac[4 * g + 2], ah, bl1[0], bl1[1]);
                mma_bf16(ac[4 * g + 3], ah, bl1[2], bl1[3]);
            }
        }
    }
}

__global__ void __launch_bounds__(NTHREADS, 2)
sofa_kernel(const float* __restrict__ alpha,
            const float* __restrict__ w0g, const float* __restrict__ w3g,
            const float* __restrict__ b0g, const float* __restrict__ b1g,
            const float* __restrict__ b2g, const float* __restrict__ b3g,
            const float* __restrict__ sqrtag, float* __restrict__ out) {
    extern __shared__ char smem[];
    const uint32_t sb = smem_u32(smem);
    const int tid = threadIdx.x;
    const int wid = tid >> 5, lane = tid & 31;
    const int mq = wid & 3, nh = wid >> 2;          // warp = (32-row M-tile, 64-col N-half)
    const int g8 = lane >> 2, t4 = lane & 3;        // D frag coords
    const int n = blockIdx.y, tile = blockIdx.x, base = tile * BT;
    const size_t woff = (size_t)n * WPC;

    // ---- layer 0: B[k=j][c=2s|2s+1] = {h0, dh0}, STS.128 pairs
    {
        const float* w0n = w0g + n * HD;
        const float* b0n = b0g + n * HD;
#pragma unroll 1
        for (int it = 0; it < 4; it++) {
            const int task = tid + 256 * it;        // 0..1023 = (j, 8-sample group)
            const int j = task >> 3, sgl = task & 7;
            const float w = w0n[j], bb = b0n[j];
            uint32_t hw[8], lw[8];
#pragma unroll
            for (int q = 0; q < 8; q++) {
                const float a = alpha[base + sgl * 8 + q];  // < 4097
                const float pre = fmaf(w, a, bb);
                const float h = pre > 0.f ? pre : 0.f;
                const float d = pre > 0.f ? w : 0.f;
                split2(h, d, hw[q], lw[q]);
            }
            const int rowb = j * BKB + sgl * 32;
            *(uint4*)(smem + OFF_BHI + rowb)      = make_uint4(hw[0], hw[1], hw[2], hw[3]);
            *(uint4*)(smem + OFF_BHI + rowb + 16) = make_uint4(hw[4], hw[5], hw[6], hw[7]);
            *(uint4*)(smem + OFF_BLO + rowb)      = make_uint4(lw[0], lw[1], lw[2], lw[3]);
            *(uint4*)(smem + OFF_BLO + rowb + 16) = make_uint4(lw[4], lw[5], lw[6], lw[7]);
        }
    }
    __syncthreads();

    // ---- layer 1 GEMM
    float acc[2][8][4];
#pragma unroll
    for (int t = 0; t < 2; t++)
#pragma unroll
        for (int a_ = 0; a_ < 8; a_++)
#pragma unroll
            for (int b_ = 0; b_ < 4; b_++) acc[t][a_][b_] = 0.f;
    gemm_layer(acc, sb, (const uint4*)(g_w1hi + woff), (const uint4*)(g_w1lo + woff),
               mq, nh, lane);
    __syncthreads();    // all B reads done before overwrite

    // ---- layer-1 epilogue via stmatrix back into B
    {
        const int h8 = (lane >> 3) & 1, v8 = (lane >> 4) & 1, lr = lane & 7;
#pragma unroll
        for (int t = 0; t < 2; t++) {
            const int i0 = 32 * mq + 16 * t + g8;
            const float bias0 = b1g[n * HD + i0];
            const float bias1 = b1g[n * HD + i0 + 8];
            const uint32_t st_hi = sb + OFF_BHI
                + (uint32_t)((32 * mq + 16 * t + 8 * h8 + lr) * BKB)
                + (uint32_t)((64 * nh + 8 * v8) * 2);
            const uint32_t st_lo = st_hi + (uint32_t)(OFF_BLO - OFF_BHI);
#pragma unroll
            for (int v = 0; v < 8; v += 2) {
                uint32_t h0, h1, h2, h3, l0, l1, l2, l3;
                {
                    const float p = acc[t][v][0] + bias0;
                    split2(p > 0.f ? p : 0.f, p > 0.f ? acc[t][v][1] : 0.f, h0, l0);
                }
                {
                    const float p = acc[t][v][2] + bias1;
                    split2(p > 0.f ? p : 0.f, p > 0.f ? acc[t][v][3] : 0.f, h1, l1);
                }
                {
                    const float p = acc[t][v + 1][0] + bias0;
                    split2(p > 0.f ? p : 0.f, p > 0.f ? acc[t][v + 1][1] : 0.f, h2, l2);
                }
                {
                    const float p = acc[t][v + 1][2] + bias1;
                    split2(p > 0.f ? p : 0.f, p > 0.f ? acc[t][v + 1][3] : 0.f, h3, l3);
                }
                stsm4(st_hi + (uint32_t)(v * 16), h0, h1, h2, h3);
                stsm4(st_lo + (uint32_t)(v * 16), l0, l1, l2, l3);
            }
        }
    }
    __syncthreads();

    // ---- layer 2 GEMM
#pragma unroll
    for (int t = 0; t < 2; t++)
#pragma unroll
        for (int a_ = 0; a_ < 8; a_++)
#pragma unroll
            for (int b_ = 0; b_ < 4; b_++) acc[t][a_][b_] = 0.f;
    gemm_layer(acc, sb, (const uint4*)(g_w2hi + woff), (const uint4*)(g_w2lo + woff),
               mq, nh, lane);

    // ---- fused layer-2 epilogue + layer-3 dot, straight from acc fragments.
    // Thread holds h2/dh2 for i in {i00, i00+8, i00+16, i00+24}-ish (2 tiles x 2 rows)
    // and s = 32*nh + 4*nt + t4. Reduce over the 8 g8-lanes via shfl_xor.
    {
        const float* w3n = w3g + n * HD;
        float w3v[2][2], b2v[2][2];
#pragma unroll
        for (int t = 0; t < 2; t++) {
            const int i0 = 32 * mq + 16 * t + g8;
            w3v[t][0] = w3n[i0];
            w3v[t][1] = w3n[i0 + 8];
            b2v[t][0] = b2g[n * HD + i0];
            b2v[t][1] = b2g[n * HD + i0 + 8];
        }
        float* redv = (float*)(smem + OFF_RED);     // [mq][64]
        float* redt = redv + 256;
#pragma unroll
        for (int nt = 0; nt < 8; nt++) {
            float sv = 0.f, st = 0.f;
#pragma unroll
            for (int t = 0; t < 2; t++) {
                const float p0 = acc[t][nt][0] + b2v[t][0];
                if (p0 > 0.f) {
                    sv = fmaf(w3v[t][0], p0, sv);
                    st = fmaf(w3v[t][0], acc[t][nt][1], st);
                }
                const float p1 = acc[t][nt][2] + b2v[t][1];
                if (p1 > 0.f) {
                    sv = fmaf(w3v[t][1], p1, sv);
                    st = fmaf(w3v[t][1], acc[t][nt][3], st);
                }
            }
#pragma unroll
            for (int m = 4; m <= 16; m <<= 1) {
                sv += __shfl_xor_sync(0xFFFFFFFFu, sv, m);
                st += __shfl_xor_sync(0xFFFFFFFFu, st, m);
            }
            if (g8 == 0) {
                const int s = 32 * nh + 4 * nt + t4;
                redv[mq * 64 + s] = sv;
                redt[mq * 64 + s] = st;
            }
        }
    }
    __syncthreads();

    // ---- trig epilogue: 256 threads = 64 samples x 4 output kinds; __sincosf
    {
        const int bl = tid & 63, kind = tid >> 6;
        const int jg = base + bl;
        if (jg < BHALF) {
            const float* redv = (const float*)(smem + OFF_RED);
            const float* redt = redv + 256;
            const float v = redv[bl] + redv[64 + bl] + redv[128 + bl]
                          + redv[192 + bl] + b3g[n];
            const float t = redt[bl] + redt[64 + bl] + redt[128 + bl]
                          + redt[192 + bl];
            const float bsq = v * v;
            const float dbv = 2.f * v * t;
            float a = sqrtag[n]; a = a * a;
            const size_t NL = (size_t)NCUR * LFULL;
            const size_t o  = (size_t)n * LFULL + jg;
            float s, c;
            __sincosf(alpha[jg], &s, &c);
            const bool mir = (jg < BHALF - 1);
            const int l = 2 * (BHALF - 1) - jg;
            float s2 = 0.f, c2 = 0.f;
            if (mir) __sincosf(alpha[l], &s2, &c2);
            const size_t o2 = (size_t)n * LFULL + l;
            switch (kind) {
                case 0:
                    out[o] = a * (c - 1.f);
                    if (mir) out[o2] = a * (c2 - 1.f);
                    break;
                case 1:
                    out[NL + o] = bsq * s;
                    if (mir) out[NL + o2] = bsq * s2;
                    break;
                case 2:
                    out[2 * NL + o] = -a * s;
                    if (mir) out[2 * NL + o2] = -a * s2;
                    break;
                default:
                    out[3 * NL + o] = fmaf(bsq, c, dbv * s);
                    if (mir) out[3 * NL + o2] = fmaf(bsq, c2, -dbv * s2);
            }
        }
    }
}

extern "C" void kernel_launch(void* const* d_in, const int* in_sizes, int n_in,
                              void* d_out, int out_size) {
    (void)in_sizes; (void)n_in; (void)out_size;
    const float* alpha  = (const float*)d_in[0];
    const float* w0     = (const float*)d_in[1];
    const float* w1     = (const float*)d_in[2];
    const float* w2     = (const float*)d_in[3];
    const float* w3     = (const float*)d_in[4];
    const float* b0     = (const float*)d_in[5];
    const float* b1     = (const float*)d_in[6];
    const float* b2     = (const float*)d_in[7];
    const float* b3     = (const float*)d_in[8];
    const float* sqrt_a = (const float*)d_in[9];
    float* out = (float*)d_out;

    split_w_kernel<<<(NCUR * WPC + 255) / 256, 256>>>(w1, w2);

    cudaFuncSetAttribute(sofa_kernel, cudaFuncAttributeMaxDynamicSharedMemorySize,
                         SMEM_BYTES);
    dim3 grid(NTILES, NCUR);   // (33, 128)
    sofa_kernel<<<grid, NTHREADS, SMEM_BYTES>>>(alpha, w0, w3,
                                                b0, b1, b2, b3, sqrt_a, out);
}

// round 17
// speedup vs baseline: 1.8329x; 1.0181x over previous
#include <cuda_runtime.h>
#include <cuda_bf16.h>
#include <math.h>
#include <stdint.h>

// SofaNetEllipse R16: R15 + the block split into two independent 128-thread
// column-half pipelines (named barriers, bar.sync 1+nh). Each half fills,
// GEMMs, and epilogues only its own 64 B-columns; halves converge once with a
// full __syncthreads before the trig tail. Fills tensor-pipe bubbles with the
// other half's scalar work. Math identical to R15.

typedef unsigned long long ull;

namespace {
constexpr int HD = 128, NCUR = 128, LFULL = 4097, BHALF = 2049, BT = 64;
constexpr int NTILES   = 33;             // 33*64 = 2112 >= 2049
constexpr int NTHREADS = 256;
constexpr int BKB = 272;                 // B k-row stride bytes (128 c-cols*2B + 16 pad)
constexpr int OFF_BHI = 0;
constexpr int OFF_BLO = OFF_BHI + HD * BKB;   // 34816
constexpr int OFF_RED = 69632;           // past B: 2KB red arrays
constexpr int SMEM_BYTES = OFF_RED + 2048;    // 71680 -> 2 blocks/SM
constexpr int WPC = 8192;                // fragment-order words per curve (128*128/2)
}

// W1/W2 in bf16 hi/lo, MMA-fragment order:
// word idx = ((n*8+mt)*8 + kk)*128 + lane*4 + q,
// q encodes (row+8*(q&1), k+8*(q>>1)), word = {bf16(k), bf16(k+1)}.
__device__ uint32_t g_w1hi[NCUR * WPC];
__device__ uint32_t g_w1lo[NCUR * WPC];
__device__ uint32_t g_w2hi[NCUR * WPC];
__device__ uint32_t g_w2lo[NCUR * WPC];

__device__ __forceinline__ uint32_t smem_u32(const void* p) {
    uint32_t a;
    asm("{ .reg .u64 t; cvta.to.shared.u64 t, %1; cvt.u32.u64 %0, t; }" : "=r"(a) : "l"(p));
    return a;
}
__device__ __forceinline__ void ldsm4t(uint32_t (&r)[4], uint32_t addr) {
    asm volatile("ldmatrix.sync.aligned.m8n8.x4.trans.shared.b16 {%0,%1,%2,%3}, [%4];"
                 : "=r"(r[0]), "=r"(r[1]), "=r"(r[2]), "=r"(r[3]) : "r"(addr));
}
__device__ __forceinline__ void stsm4(uint32_t addr, uint32_t r0, uint32_t r1,
                                      uint32_t r2, uint32_t r3) {
    asm volatile("stmatrix.sync.aligned.m8n8.x4.shared.b16 [%0], {%1,%2,%3,%4};"
                 :: "r"(addr), "r"(r0), "r"(r1), "r"(r2), "r"(r3) : "memory");
}
__device__ __forceinline__ void mma_bf16(float (&d)[4], const uint32_t* a,
                                         uint32_t b0, uint32_t b1) {
    asm volatile(
        "mma.sync.aligned.m16n8k16.row.col.f32.bf16.bf16.f32 "
        "{%0,%1,%2,%3}, {%4,%5,%6,%7}, {%8,%9}, {%0,%1,%2,%3};"
        : "+f"(d[0]), "+f"(d[1]), "+f"(d[2]), "+f"(d[3])
        : "r"(a[0]), "r"(a[1]), "r"(a[2]), "r"(a[3]), "r"(b0), "r"(b1));
}
// half-pipeline barrier: 128 threads of column-half nh (warps are contiguous)
__device__ __forceinline__ void half_bar(int nh) {
    asm volatile("bar.sync %0, 128;" :: "r"(1 + nh) : "memory");
}
// truncation split of pair (x,y): hi = upper 16 bits, lo = rn(residual)
__device__ __forceinline__ void split2(float x, float y, uint32_t& hi, uint32_t& lo) {
    const uint32_t xb = __float_as_uint(x), yb = __float_as_uint(y);
    uint32_t h;
    asm("prmt.b32 %0, %1, %2, 0x7632;" : "=r"(h) : "r"(xb), "r"(yb));  // {x.hi16, y.hi16}
    hi = h;
    const float lx = x - __uint_as_float(xb & 0xFFFF0000u);
    const float ly = y - __uint_as_float(yb & 0xFFFF0000u);
    asm("cvt.rn.bf16x2.f32 %0, %2, %1;" : "=r"(lo) : "f"(lx), "f"(ly));
}

// ---- prologue: fp32 W1/W2 -> bf16 hi/lo in fragment order
__global__ void split_w_kernel(const float* __restrict__ w1, const float* __restrict__ w2) {
    const int idx = blockIdx.x * blockDim.x + threadIdx.x;      // word index
    if (idx >= NCUR * WPC) return;
    const int n = idx >> 13, r = idx & (WPC - 1);
    const int mt = r >> 10, kk = (r >> 7) & 7, lane = (r >> 2) & 31, q = r & 3;
    const int i  = 16 * mt + (lane >> 2) + 8 * (q & 1);
    const int k0 = 16 * kk + 2 * (lane & 3) + 8 * (q >> 1);
    const size_t src = ((size_t)n * HD + i) * HD + k0;
    {
        uint32_t hi, lo;
        split2(w1[src], w1[src + 1], hi, lo);
        g_w1hi[idx] = hi; g_w1lo[idx] = lo;
    }
    {
        uint32_t hi, lo;
        split2(w2[src], w2[src + 1], hi, lo);
        g_w2hi[idx] = hi; g_w2lo[idx] = lo;
    }
}

// One layer GEMM: 3-term bf16 (Whi*Hhi + Wlo*Hhi + Whi*Hlo).
// Warp tile 32x64: M-tiles t=0,1 (rows 32mq+16t..+15), c-cols 64nh..+63.
// A fragments via coalesced LDG.128 (fragment order); B via ldmatrix.trans,
// each B frag reused by both M-tiles.
__device__ __forceinline__ void gemm_layer(float (&acc)[2][8][4], uint32_t sb,
                                           const uint4* __restrict__ ghi,
                                           const uint4* __restrict__ glo,
                                           int mq, int nh, int lane) {
    const int krow = (lane & 7) + (lane & 8);
    const uint32_t b_off = (uint32_t)(krow * BKB)
                         + (uint32_t)(128 * nh) + (uint32_t)((lane & 16));
    const uint32_t b_hi = sb + OFF_BHI + b_off;
    const uint32_t b_lo = sb + OFF_BLO + b_off;
    const int tb0 = 2 * mq * 8;                   // tile block (t=0), +8 for t=1

#pragma unroll
    for (int kk = 0; kk < 8; kk++) {
        uint4 cah[2], cal[2];
        cah[0] = __ldg(ghi + (tb0 + kk) * 32 + lane);
        cah[1] = __ldg(ghi + (tb0 + 8 + kk) * 32 + lane);
        cal[0] = __ldg(glo + (tb0 + kk) * 32 + lane);
        cal[1] = __ldg(glo + (tb0 + 8 + kk) * 32 + lane);
        const uint32_t kb = (uint32_t)kk * (16u * BKB);
#pragma unroll
        for (int g = 0; g < 2; g++) {
            const uint32_t go = kb + 64u * g;             // +32 c-cols per group
            uint32_t bh0[4], bh1[4], bl0[4], bl1[4];
            ldsm4t(bh0, b_hi + go);
            ldsm4t(bh1, b_hi + go + 32u);                 // +16 c-cols
            ldsm4t(bl0, b_lo + go);
            ldsm4t(bl1, b_lo + go + 32u);
#pragma unroll
            for (int t = 0; t < 2; t++) {
                const uint32_t* ah = (const uint32_t*)&cah[t];
                const uint32_t* al = (const uint32_t*)&cal[t];
                float (*ac)[4] = acc[t];
                mma_bf16(ac[4 * g + 0], ah, bh0[0], bh0[1]);
                mma_bf16(ac[4 * g + 1], ah, bh0[2], bh0[3]);
                mma_bf16(ac[4 * g + 2], ah, bh1[0], bh1[1]);
                mma_bf16(ac[4 * g + 3], ah, bh1[2], bh1[3]);
                mma_bf16(ac[4 * g + 0], al, bh0[0], bh0[1]);
                mma_bf16(ac[4 * g + 1], al, bh0[2], bh0[3]);
                mma_bf16(ac[4 * g + 2], al, bh1[0], bh1[1]);
                mma_bf16(ac[4 * g + 3], al, bh1[2], bh1[3]);
                mma_bf16(ac[4 * g + 0], ah, bl0[0], bl0[1]);
                mma_bf16(ac[4 * g + 1], ah, bl0[2], bl0[3]);
                mma_bf16(ac[4 * g + 2], ah, bl1[0], bl1[1]);
                mma_bf16(ac[4 * g + 3], ah, bl1[2], bl1[3]);
            }
        }
    }
}

__global__ void __launch_bounds__(NTHREADS, 2)
sofa_kernel(const float* __restrict__ alpha,
            const float* __restrict__ w0g, const float* __restrict__ w3g,
            const float* __restrict__ b0g, const float* __restrict__ b1g,
            const float* __restrict__ b2g, const float* __restrict__ b3g,
            const float* __restrict__ sqrtag, float* __restrict__ out) {
    extern __shared__ char smem[];
    const uint32_t sb = smem_u32(smem);
    const int tid = threadIdx.x;
    const int wid = tid >> 5, lane = tid & 31;
    const int mq = wid & 3, nh = wid >> 2;          // warp = (32-row M-tile, 64-col N-half)
    const int g8 = lane >> 2, t4 = lane & 3;        // D frag coords
    const int n = blockIdx.y, tile = blockIdx.x, base = tile * BT;
    const size_t woff = (size_t)n * WPC;

    // ---- layer 0: each half fills its OWN 64 c-cols (samples 32*nh..+31)
    {
        const int t128 = tid & 127;
        const float* w0n = w0g + n * HD;
        const float* b0n = b0g + n * HD;
#pragma unroll 1
        for (int it = 0; it < 4; it++) {
            const int task = t128 + 128 * it;       // 0..511 = (j, 8-sample group/4)
            const int j = task >> 2, sgl = task & 3;
            const float w = w0n[j], bb = b0n[j];
            uint32_t hw[8], lw[8];
#pragma unroll
            for (int q = 0; q < 8; q++) {
                const float a = alpha[base + 32 * nh + sgl * 8 + q];   // < 4097
                const float pre = fmaf(w, a, bb);
                const float h = pre > 0.f ? pre : 0.f;
                const float d = pre > 0.f ? w : 0.f;
                split2(h, d, hw[q], lw[q]);
            }
            const int rowb = j * BKB + (4 * nh + sgl) * 32;
            *(uint4*)(smem + OFF_BHI + rowb)      = make_uint4(hw[0], hw[1], hw[2], hw[3]);
            *(uint4*)(smem + OFF_BHI + rowb + 16) = make_uint4(hw[4], hw[5], hw[6], hw[7]);
            *(uint4*)(smem + OFF_BLO + rowb)      = make_uint4(lw[0], lw[1], lw[2], lw[3]);
            *(uint4*)(smem + OFF_BLO + rowb + 16) = make_uint4(lw[4], lw[5], lw[6], lw[7]);
        }
    }
    half_bar(nh);

    // ---- layer 1 GEMM (own column half)
    float acc[2][8][4];
#pragma unroll
    for (int t = 0; t < 2; t++)
#pragma unroll
        for (int a_ = 0; a_ < 8; a_++)
#pragma unroll
            for (int b_ = 0; b_ < 4; b_++) acc[t][a_][b_] = 0.f;
    gemm_layer(acc, sb, (const uint4*)(g_w1hi + woff), (const uint4*)(g_w1lo + woff),
               mq, nh, lane);
    half_bar(nh);       // own half's B reads done before overwrite

    // ---- layer-1 epilogue via stmatrix back into own half's B columns
    {
        const int h8 = (lane >> 3) & 1, v8 = (lane >> 4) & 1, lr = lane & 7;
#pragma unroll
        for (int t = 0; t < 2; t++) {
            const int i0 = 32 * mq + 16 * t + g8;
            const float bias0 = b1g[n * HD + i0];
            const float bias1 = b1g[n * HD + i0 + 8];
            const uint32_t st_hi = sb + OFF_BHI
                + (uint32_t)((32 * mq + 16 * t + 8 * h8 + lr) * BKB)
                + (uint32_t)((64 * nh + 8 * v8) * 2);
            const uint32_t st_lo = st_hi + (uint32_t)(OFF_BLO - OFF_BHI);
#pragma unroll
            for (int v = 0; v < 8; v += 2) {
                uint32_t h0, h1, h2, h3, l0, l1, l2, l3;
                {
                    const float p = acc[t][v][0] + bias0;
                    split2(p > 0.f ? p : 0.f, p > 0.f ? acc[t][v][1] : 0.f, h0, l0);
                }
                {
                    const float p = acc[t][v][2] + bias1;
                    split2(p > 0.f ? p : 0.f, p > 0.f ? acc[t][v][3] : 0.f, h1, l1);
                }
                {
                    const float p = acc[t][v + 1][0] + bias0;
                    split2(p > 0.f ? p : 0.f, p > 0.f ? acc[t][v + 1][1] : 0.f, h2, l2);
                }
                {
                    const float p = acc[t][v + 1][2] + bias1;
                    split2(p > 0.f ? p : 0.f, p > 0.f ? acc[t][v + 1][3] : 0.f, h3, l3);
                }
                stsm4(st_hi + (uint32_t)(v * 16), h0, h1, h2, h3);
                stsm4(st_lo + (uint32_t)(v * 16), l0, l1, l2, l3);
            }
        }
    }
    half_bar(nh);

    // ---- layer 2 GEMM (own column half)
#pragma unroll
    for (int t = 0; t < 2; t++)
#pragma unroll
        for (int a_ = 0; a_ < 8; a_++)
#pragma unroll
            for (int b_ = 0; b_ < 4; b_++) acc[t][a_][b_] = 0.f;
    gemm_layer(acc, sb, (const uint4*)(g_w2hi + woff), (const uint4*)(g_w2lo + woff),
               mq, nh, lane);

    // ---- fused layer-2 epilogue + layer-3 dot from acc fragments (own half)
    {
        const float* w3n = w3g + n * HD;
        float w3v[2][2], b2v[2][2];
#pragma unroll
        for (int t = 0; t < 2; t++) {
            const int i0 = 32 * mq + 16 * t + g8;
            w3v[t][0] = w3n[i0];
            w3v[t][1] = w3n[i0 + 8];
            b2v[t][0] = b2g[n * HD + i0];
            b2v[t][1] = b2g[n * HD + i0 + 8];
        }
        float* redv = (float*)(smem + OFF_RED);     // [mq][64]
        float* redt = redv + 256;
#pragma unroll
        for (int nt = 0; nt < 8; nt++) {
            float sv = 0.f, st = 0.f;
#pragma unroll
            for (int t = 0; t < 2; t++) {
                const float p0 = acc[t][nt][0] + b2v[t][0];
                if (p0 > 0.f) {
                    sv = fmaf(w3v[t][0], p0, sv);
                    st = fmaf(w3v[t][0], acc[t][nt][1], st);
                }
                const float p1 = acc[t][nt][2] + b2v[t][1];
                if (p1 > 0.f) {
                    sv = fmaf(w3v[t][1], p1, sv);
                    st = fmaf(w3v[t][1], acc[t][nt][3], st);
                }
            }
#pragma unroll
            for (int m = 4; m <= 16; m <<= 1) {
                sv += __shfl_xor_sync(0xFFFFFFFFu, sv, m);
                st += __shfl_xor_sync(0xFFFFFFFFu, st, m);
            }
            if (g8 == 0) {
                const int s = 32 * nh + 4 * nt + t4;
                redv[mq * 64 + s] = sv;
                redt[mq * 64 + s] = st;
            }
        }
    }
    __syncthreads();    // halves converge once, before trig reads all samples

    // ---- trig epilogue: 256 threads = 64 samples x 4 output kinds; __sincosf
    {
        const int bl = tid & 63, kind = tid >> 6;
        const int jg = base + bl;
        if (jg < BHALF) {
            const float* redv = (const float*)(smem + OFF_RED);
            const float* redt = redv + 256;
            const float v = redv[bl] + redv[64 + bl] + redv[128 + bl]
                          + redv[192 + bl] + b3g[n];
            const float t = redt[bl] + redt[64 + bl] + redt[128 + bl]
                          + redt[192 + bl];
            const float bsq = v * v;
            const float dbv = 2.f * v * t;
            float a = sqrtag[n]; a = a * a;
            const size_t NL = (size_t)NCUR * LFULL;
            const size_t o  = (size_t)n * LFULL + jg;
            float s, c;
            __sincosf(alpha[jg], &s, &c);
            const bool mir = (jg < BHALF - 1);
            const int l = 2 * (BHALF - 1) - jg;
            float s2 = 0.f, c2 = 0.f;
            if (mir) __sincosf(alpha[l], &s2, &c2);
            const size_t o2 = (size_t)n * LFULL + l;
            switch (kind) {
                case 0:
                    out[o] = a * (c - 1.f);
                    if (mir) out[o2] = a * (c2 - 1.f);
                    break;
                case 1:
                    out[NL + o] = bsq * s;
                    if (mir) out[NL + o2] = bsq * s2;
                    break;
                case 2:
                    out[2 * NL + o] = -a * s;
                    if (mir) out[2 * NL + o2] = -a * s2;
                    break;
                default:
                    out[3 * NL + o] = fmaf(bsq, c, dbv * s);
                    if (mir) out[3 * NL + o2] = fmaf(bsq, c2, -dbv * s2);
            }
        }
    }
}

extern "C" void kernel_launch(void* const* d_in, const int* in_sizes, int n_in,
                              void* d_out, int out_size) {
    (void)in_sizes; (void)n_in; (void)out_size;
    const float* alpha  = (const float*)d_in[0];
    const float* w0     = (const float*)d_in[1];
    const float* w1     = (const float*)d_in[2];
    const float* w2     = (const float*)d_in[3];
    const float* w3     = (const float*)d_in[4];
    const float* b0     = (const float*)d_in[5];
    const float* b1     = (const float*)d_in[6];
    const float* b2     = (const float*)d_in[7];
    const float* b3     = (const float*)d_in[8];
    const float* sqrt_a = (const float*)d_in[9];
    float* out = (float*)d_out;

    split_w_kernel<<<(NCUR * WPC + 255) / 256, 256>>>(w1, w2);

    cudaFuncSetAttribute(sofa_kernel, cudaFuncAttributeMaxDynamicSharedMemorySize,
                         SMEM_BYTES);
    dim3 grid(NTILES, NCUR);   // (33, 128)
    sofa_kernel<<<grid, NTHREADS, SMEM_BYTES>>>(alpha, w0, w3,
                                                b0, b1, b2, b3, sqrt_a, out);
}